// round 8
// baseline (speedup 1.0000x reference)
#include <cuda_runtime.h>
#include <stdint.h>

#define T_SEQ 2048
#define BATCH 64
#define INPUT 16
#define HEADS 8
#define HID   64
#define GATES 256   // 4*HID

#define FMA2(acc, a, b) \
    asm("fma.rn.f32x2 %0, %1, %2, %0;" : "+l"(acc) : "l"(a), "l"(b))
#define ADD2(d, a, b) \
    asm("add.rn.f32x2 %0, %1, %2;" : "=l"(d) : "l"(a), "l"(b))
#define PACK2(d, lo, hi) \
    asm("mov.b64 %0, {%1, %2};" : "=l"(d) : "f"(lo), "f"(hi))
#define UNPACK2(lo, hi, s) \
    asm("mov.b64 {%0, %1}, %2;" : "=f"(lo), "=f"(hi) : "l"(s))

// Pre-fill outputs: out[t,b,h] = b_lin[h]; lstm_out = 0. (d_out is poisoned.)
__global__ __launch_bounds__(256)
void init_out_kernel(const float* __restrict__ b_lin, float* __restrict__ o) {
    const int idx = blockIdx.x * 256 + threadIdx.x;
    const int n_out = T_SEQ * BATCH * HEADS;
    const int n_tot = n_out + T_SEQ * BATCH * HID;
    if (idx < n_out)      o[idx] = b_lin[idx & 7];
    else if (idx < n_tot) o[idx] = 0.0f;
}

// One CTA per (batch, head) chain, 256 threads.
// Thread t -> unit k = t>>2, gate quarter q = t&3, gate row g = q*64 + k.
// The 4 gates of unit k sit in 4 adjacent lanes -> SHFL exchange, no barrier.
// Double-buffered sh_h/sh_x -> ONE __syncthreads per step.
__global__ __launch_bounds__(256, 2)
void lstm_chain_kernel(const float* __restrict__ x,
                       const float* __restrict__ W_ih,
                       const float* __restrict__ W_hh,
                       const float* __restrict__ b_ih,
                       const float* __restrict__ b_hh,
                       const float* __restrict__ W_lin,
                       float* __restrict__ out,       // (T,B,H)
                       float* __restrict__ lstm_out)  // (T,B,HID)
{
    const int b = blockIdx.x >> 3;
    const int h = blockIdx.x & 7;
    const int t_id = threadIdx.x;
    const int k = t_id >> 2;        // hidden unit 0..63
    const int q = t_id & 3;         // gate: 0:i 1:f 2:g 3:o
    const int g = q * 64 + k;       // gate row in W_hh/W_ih
    const int lane = t_id & 31;
    const int base = lane & ~3;     // first lane of this unit's 4-group

    __shared__ __align__(16) float sh_h[2][HID];
    __shared__ __align__(16) float sh_x[2][INPUT];

    // Pack this gate row's weights into f32x2 registers (once).
    uint64_t w[HID / 2];    // 32 u64 = 64 regs
    uint64_t xw[INPUT / 2]; // 8 u64  = 16 regs
    {
        const float* wr = W_hh + (h * GATES + g) * HID;
#pragma unroll
        for (int p = 0; p < HID / 2; p++) PACK2(w[p], wr[2 * p], wr[2 * p + 1]);
        const float* xr = W_ih + (h * GATES + g) * INPUT;
#pragma unroll
        for (int p = 0; p < INPUT / 2; p++) PACK2(xw[p], xr[2 * p], xr[2 * p + 1]);
    }
    const float bias = b_ih[h * GATES + g] + b_hh[h * GATES + g];
    uint64_t bias2; PACK2(bias2, bias, 0.0f);

    // Unified activation: r = 2/(1+exp(s*z)); act = beta*r + delta
    //  sigmoid: s=-1, beta=0.5, delta=0     tanh: s=-2, beta=1, delta=-1
    const float a_s    = (q == 2) ? -2.0f : -1.0f;
    const float a_beta = (q == 2) ?  1.0f :  0.5f;
    const float a_delt = (q == 2) ? -1.0f :  0.0f;

    const bool is_q0 = (q == 0);
    const float wl = is_q0 ? W_lin[h * HID + k] : 0.0f;

    float c = 0.0f;
    if (t_id < HID)   { sh_h[0][t_id] = 0.0f; }
    if (t_id < INPUT) { sh_x[0][t_id] = x[b * INPUT + t_id]; }
    __syncthreads();

    float* out_p  = out + (size_t)b * HEADS + h;
    float* lstm_p = lstm_out + (size_t)b * HID + k;

#pragma unroll 1
    for (int t = 0; t < T_SEQ; t++) {
        const int p = t & 1;

        // Prefetch next x (threads 0..15), hidden under the matvec.
        float xreg = 0.0f;
        if (t_id < INPUT && t + 1 < T_SEQ)
            xreg = x[((t + 1) * BATCH + b) * INPUT + t_id];

        // z = bias + W_ih[g,:].x_t + W_hh[g,:].h_prev   (packed f32x2)
        uint64_t a0 = bias2, a1 = 0ull, a2 = 0ull, a3 = 0ull;
        const ulonglong2* x2 = (const ulonglong2*)sh_x[p];
#pragma unroll
        for (int u = 0; u < INPUT / 4; u++) {
            ulonglong2 v = x2[u];
            FMA2(a0, xw[2 * u],     v.x);
            FMA2(a1, xw[2 * u + 1], v.y);
        }
        const ulonglong2* h2 = (const ulonglong2*)sh_h[p];
#pragma unroll
        for (int u = 0; u < HID / 4; u++) {
            ulonglong2 v = h2[u];
            FMA2(a2, w[2 * u],     v.x);
            FMA2(a3, w[2 * u + 1], v.y);
        }
        uint64_t s64, u64v;
        ADD2(s64, a0, a1); ADD2(u64v, a2, a3); ADD2(s64, s64, u64v);
        float lo, hi;
        UNPACK2(lo, hi, s64);
        const float z = lo + hi;

        // activation (divergence-free)
        const float e = __expf(a_s * z);
        const float r = __fdividef(2.0f, 1.0f + e);
        const float act = fmaf(a_beta, r, a_delt);

        // gather the 4 gates of unit k into lane q==0 (3 shuffles, no barrier)
        const float fv = __shfl_sync(0xffffffffu, act, base + 1, 32);
        const float gv = __shfl_sync(0xffffffffu, act, base + 2, 32);
        const float ov = __shfl_sync(0xffffffffu, act, base + 3, 32);

        if (is_q0) {
            c = fmaf(fv, c, act * gv);            // act == i gate here
            const float e2 = __expf(-2.0f * c);
            const float th = __fdividef(2.0f, 1.0f + e2) - 1.0f;
            const float hv = ov * th;
            sh_h[1 - p][k] = hv;
            atomicAdd(out_p,  hv * wl);           // RED.ADD.F32
            atomicAdd(lstm_p, hv);                // RED.ADD.F32
        }
        if (t_id < INPUT) sh_x[1 - p][t_id] = xreg;

        __syncthreads();   // single barrier: next step reads buffer 1-p

        out_p  += BATCH * HEADS;
        lstm_p += BATCH * HID;
    }
}

extern "C" void kernel_launch(void* const* d_in, const int* in_sizes, int n_in,
                              void* d_out, int out_size) {
    const float* x     = (const float*)d_in[0];  // (T,B,I)
    const float* W_ih  = (const float*)d_in[1];  // (H,4h,I)
    const float* W_hh  = (const float*)d_in[2];  // (H,4h,h)
    const float* b_ih  = (const float*)d_in[3];  // (H,4h)
    const float* b_hh  = (const float*)d_in[4];  // (H,4h)
    const float* W_lin = (const float*)d_in[5];  // (H,h)
    const float* b_lin = (const float*)d_in[6];  // (H,)

    float* out      = (float*)d_out;                          // (T,B,H)
    float* lstm_out = out + (size_t)T_SEQ * BATCH * HEADS;    // (T,B,hid)

    const int n_tot = T_SEQ * BATCH * (HEADS + HID);
    init_out_kernel<<<(n_tot + 255) / 256, 256>>>(b_lin, (float*)d_out);
    lstm_chain_kernel<<<BATCH * HEADS, 256>>>(x, W_ih, W_hh, b_ih, b_hh,
                                              W_lin, out, lstm_out);
}

// round 11
// speedup vs baseline: 1.8376x; 1.8376x over previous
#include <cuda_runtime.h>
#include <stdint.h>

#define T_SEQ 2048
#define BATCH 64
#define INPUT 16
#define HEADS 8
#define HID   64
#define GATES 256   // 4*HID

#define FMA2(acc, a, b) \
    asm("fma.rn.f32x2 %0, %1, %2, %0;" : "+l"(acc) : "l"(a), "l"(b))
#define ADD2(d, a, b) \
    asm("add.rn.f32x2 %0, %1, %2;" : "=l"(d) : "l"(a), "l"(b))
#define PACK2(d, lo, hi) \
    asm("mov.b64 %0, {%1, %2};" : "=l"(d) : "f"(lo), "f"(hi))
#define UNPACK2(lo, hi, s) \
    asm("mov.b64 {%0, %1}, %2;" : "=f"(lo), "=f"(hi) : "l"(s))

__device__ __forceinline__ float tanh_hw(float x) {
    float r;
    asm("tanh.approx.f32 %0, %1;" : "=f"(r) : "f"(x));
    return r;
}
// sigmoid(x) = 0.5*tanh(x/2) + 0.5   (1 MUFU + 2 FMA-class ops)
__device__ __forceinline__ float sigmoid_hw(float x) {
    return fmaf(0.5f, tanh_hw(0.5f * x), 0.5f);
}

// Pre-fill outputs: out[t,b,h] = b_lin[h]; lstm_out = 0. (d_out is poisoned.)
__global__ __launch_bounds__(256)
void init_out_kernel(const float* __restrict__ b_lin, float* __restrict__ o) {
    const int idx = blockIdx.x * 256 + threadIdx.x;
    const int n_out = T_SEQ * BATCH * HEADS;
    const int n_tot = n_out + T_SEQ * BATCH * HID;
    if (idx < n_out)      o[idx] = b_lin[idx & 7];
    else if (idx < n_tot) o[idx] = 0.0f;
}

// One CTA per (batch, head) chain. 256 threads; thread g owns gate row g.
// (R4 structure: smem gate exchange, 2 barriers/step, epilogue in warps 0-1.)
__global__ __launch_bounds__(256, 2)
void lstm_chain_kernel(const float* __restrict__ x,
                       const float* __restrict__ W_ih,
                       const float* __restrict__ W_hh,
                       const float* __restrict__ b_ih,
                       const float* __restrict__ b_hh,
                       const float* __restrict__ W_lin,
                       float* __restrict__ out,       // (T,B,H)
                       float* __restrict__ lstm_out)  // (T,B,HID)
{
    const int b = blockIdx.x >> 3;
    const int h = blockIdx.x & 7;
    const int g = threadIdx.x;

    __shared__ __align__(16) float sh_h[HID];
    __shared__ __align__(16) float sh_x[INPUT];
    __shared__ float sh_act[GATES];

    // Pack weights for this gate row into f32x2 registers (once).
    uint64_t w[HID / 2];    // 32 u64 = 64 regs
    uint64_t xw[INPUT / 2]; // 8 u64  = 16 regs
    {
        const float* wr = W_hh + (h * GATES + g) * HID;
#pragma unroll
        for (int q = 0; q < HID / 2; q++) PACK2(w[q], wr[2 * q], wr[2 * q + 1]);
        const float* xr = W_ih + (h * GATES + g) * INPUT;
#pragma unroll
        for (int q = 0; q < INPUT / 2; q++) PACK2(xw[q], xr[2 * q], xr[2 * q + 1]);
    }
    const float bias = b_ih[h * GATES + g] + b_hh[h * GATES + g];
    uint64_t bias2; PACK2(bias2, bias, 0.0f);

    // Per-head linear weight for this hidden unit (lanes g<64 only)
    const float wl = (g < HID) ? W_lin[h * HID + g] : 0.0f;

    float c = 0.0f;
    if (g < HID)   sh_h[g] = 0.0f;
    if (g < INPUT) sh_x[g] = x[b * INPUT + g];   // x[t=0, b, :]
    __syncthreads();

    const int gate_type = g >> 6;  // warp-uniform: 0:i 1:f 2:g 3:o

    float* out_p  = out + (size_t)b * HEADS + h;
    float* lstm_p = lstm_out + (size_t)b * HID + (g & 63);

#pragma unroll 1
    for (int t = 0; t < T_SEQ; t++) {
        // Prefetch next x (latency hidden under the matvec)
        float xreg = 0.0f;
        if (g < INPUT && t + 1 < T_SEQ)
            xreg = x[((t + 1) * BATCH + b) * INPUT + g];

        // z = bias + W_ih[g,:].x_t + W_hh[g,:].h_prev  (packed f32x2)
        uint64_t a0 = bias2, a1 = 0ull, a2 = 0ull, a3 = 0ull;
        const ulonglong2* x2 = (const ulonglong2*)sh_x;
#pragma unroll
        for (int q = 0; q < INPUT / 4; q++) {
            ulonglong2 v = x2[q];
            FMA2(a0, xw[2 * q],     v.x);
            FMA2(a1, xw[2 * q + 1], v.y);
        }
        const ulonglong2* h2 = (const ulonglong2*)sh_h;
#pragma unroll
        for (int q = 0; q < HID / 4; q++) {
            ulonglong2 v = h2[q];
            FMA2(a2, w[2 * q],     v.x);
            FMA2(a3, w[2 * q + 1], v.y);
        }
        uint64_t s, u;
        ADD2(s, a0, a1); ADD2(u, a2, a3); ADD2(s, s, u);
        float lo, hi;
        UNPACK2(lo, hi, s);
        float z = lo + hi;

        // activation: HW tanh (gate_type warp-uniform -> no divergence cost)
        float a = (gate_type == 2) ? tanh_hw(z) : sigmoid_hw(z);
        sh_act[g] = a;
        __syncthreads();   // B1: acts visible; reads of sh_h/sh_x complete

        if (g < HID) {
            float iv = sh_act[g];
            float fv = sh_act[HID + g];
            float gv = sh_act[2 * HID + g];
            float ov = sh_act[3 * HID + g];
            c = fmaf(fv, c, iv * gv);
            float hv = ov * tanh_hw(c);
            sh_h[g] = hv;
            atomicAdd(out_p,  hv * wl);   // RED.ADD.F32 (fire-and-forget)
            atomicAdd(lstm_p, hv);        // RED.ADD.F32
        }
        if (g < INPUT) sh_x[g] = xreg;
        __syncthreads();   // B2: new sh_h/sh_x visible

        out_p  += BATCH * HEADS;
        lstm_p += BATCH * HID;
    }
}

extern "C" void kernel_launch(void* const* d_in, const int* in_sizes, int n_in,
                              void* d_out, int out_size) {
    const float* x     = (const float*)d_in[0];  // (T,B,I)
    const float* W_ih  = (const float*)d_in[1];  // (H,4h,I)
    const float* W_hh  = (const float*)d_in[2];  // (H,4h,h)
    const float* b_ih  = (const float*)d_in[3];  // (H,4h)
    const float* b_hh  = (const float*)d_in[4];  // (H,4h)
    const float* W_lin = (const float*)d_in[5];  // (H,h)
    const float* b_lin = (const float*)d_in[6];  // (H,)

    float* out      = (float*)d_out;                          // (T,B,H)
    float* lstm_out = out + (size_t)T_SEQ * BATCH * HEADS;    // (T,B,hid)

    const int n_tot = T_SEQ * BATCH * (HEADS + HID);
    init_out_kernel<<<(n_tot + 255) / 256, 256>>>(b_lin, (float*)d_out);
    lstm_chain_kernel<<<BATCH * HEADS, 256>>>(x, W_ih, W_hh, b_ih, b_hh,
                                              W_lin, out, lstm_out);
}

// round 12
// speedup vs baseline: 1.9132x; 1.0412x over previous
#include <cuda_runtime.h>
#include <stdint.h>

#define T_SEQ 2048
#define BATCH 64
#define INPUT 16
#define HEADS 8
#define HID   64
#define GATES 256   // 4*HID

#define FMA2(acc, a, b) \
    asm("fma.rn.f32x2 %0, %1, %2, %0;" : "+l"(acc) : "l"(a), "l"(b))
#define ADD2(d, a, b) \
    asm("add.rn.f32x2 %0, %1, %2;" : "=l"(d) : "l"(a), "l"(b))
#define PACK2(d, lo, hi) \
    asm("mov.b64 %0, {%1, %2};" : "=l"(d) : "f"(lo), "f"(hi))
#define UNPACK2(lo, hi, s) \
    asm("mov.b64 {%0, %1}, %2;" : "=f"(lo), "=f"(hi) : "l"(s))

__device__ __forceinline__ float tanh_hw(float x) {
    float r;
    asm("tanh.approx.f32 %0, %1;" : "=f"(r) : "f"(x));
    return r;
}
// sigmoid(x) = 0.5*tanh(x/2) + 0.5
__device__ __forceinline__ float sigmoid_hw(float x) {
    return fmaf(0.5f, tanh_hw(0.5f * x), 0.5f);
}

// Pre-fill outputs: out[t,b,h] = b_lin[h]; lstm_out = 0. (d_out is poisoned.)
__global__ __launch_bounds__(256)
void init_out_kernel(const float* __restrict__ b_lin, float* __restrict__ o) {
    const int idx = blockIdx.x * 256 + threadIdx.x;
    const int n_out = T_SEQ * BATCH * HEADS;
    const int n_tot = n_out + T_SEQ * BATCH * HID;
    if (idx < n_out)      o[idx] = b_lin[idx & 7];
    else if (idx < n_tot) o[idx] = 0.0f;
}

// One CTA per (head, batch-pair): 2 independent chains sharing register-
// resident weights. 256 CTAs -> ONE wave at occupancy 2.
// Thread g owns gate row g for BOTH chains (2 packed acc chains per chain).
// Epilogue: lanes 0-63 finish chain 0, lanes 64-127 finish chain 1.
__global__ __launch_bounds__(256, 2)
void lstm_chain2_kernel(const float* __restrict__ x,
                        const float* __restrict__ W_ih,
                        const float* __restrict__ W_hh,
                        const float* __restrict__ b_ih,
                        const float* __restrict__ b_hh,
                        const float* __restrict__ W_lin,
                        float* __restrict__ out,       // (T,B,H)
                        float* __restrict__ lstm_out)  // (T,B,HID)
{
    const int h  = blockIdx.x & 7;
    const int b0 = (blockIdx.x >> 3) * 2;
    const int g  = threadIdx.x;

    __shared__ __align__(16) float sh_h[2][HID];
    __shared__ __align__(16) float sh_x[2][INPUT];
    __shared__ float sh_act[2][GATES];

    // Pack this gate row's weights into f32x2 registers (once, shared by
    // both chains).
    uint64_t w[HID / 2];    // 32 u64 = 64 regs
    uint64_t xw[INPUT / 2]; // 8 u64  = 16 regs
    {
        const float* wr = W_hh + (h * GATES + g) * HID;
#pragma unroll
        for (int q = 0; q < HID / 2; q++) PACK2(w[q], wr[2 * q], wr[2 * q + 1]);
        const float* xr = W_ih + (h * GATES + g) * INPUT;
#pragma unroll
        for (int q = 0; q < INPUT / 2; q++) PACK2(xw[q], xr[2 * q], xr[2 * q + 1]);
    }
    const float bias = b_ih[h * GATES + g] + b_hh[h * GATES + g];
    uint64_t bias2; PACK2(bias2, bias, 0.0f);

    // Epilogue role: lanes 0-63 -> chain 0, lanes 64-127 -> chain 1.
    const int  ech = (g >> 6) & 1;       // epilogue chain (valid for g<128)
    const int  ek  = g & 63;             // epilogue hidden unit
    const bool is_epi = (g < 128);
    const float wl = is_epi ? W_lin[h * HID + ek] : 0.0f;

    float c = 0.0f;
    if (g < 128) sh_h[ech][ek] = 0.0f;
    if (g < 32)  sh_x[g >> 4][g & 15] = x[(b0 + (g >> 4)) * INPUT + (g & 15)];
    __syncthreads();

    const int gate_type = g >> 6;  // warp-uniform: 0:i 1:f 2:g 3:o

    float* out_p  = out + (size_t)(b0 + ech) * HEADS + h;
    float* lstm_p = lstm_out + (size_t)(b0 + ech) * HID + ek;

#pragma unroll 1
    for (int t = 0; t < T_SEQ; t++) {
        // Prefetch next x for both chains (threads 0-31)
        float xreg = 0.0f;
        if (g < 32 && t + 1 < T_SEQ)
            xreg = x[((t + 1) * BATCH + b0 + (g >> 4)) * INPUT + (g & 15)];

        // z_ch = bias + W_ih[g,:].x_ch + W_hh[g,:].h_ch   (packed f32x2)
        uint64_t p00 = bias2, p01 = 0ull;   // chain 0: 2 acc chains
        uint64_t p10 = bias2, p11 = 0ull;   // chain 1: 2 acc chains

        const ulonglong2* xA = (const ulonglong2*)sh_x[0];
        const ulonglong2* xB = (const ulonglong2*)sh_x[1];
#pragma unroll
        for (int q = 0; q < INPUT / 4; q++) {
            ulonglong2 vA = xA[q], vB = xB[q];
            FMA2(p00, xw[2 * q],     vA.x);
            FMA2(p01, xw[2 * q + 1], vA.y);
            FMA2(p10, xw[2 * q],     vB.x);
            FMA2(p11, xw[2 * q + 1], vB.y);
        }
        const ulonglong2* hA = (const ulonglong2*)sh_h[0];
        const ulonglong2* hB = (const ulonglong2*)sh_h[1];
#pragma unroll
        for (int q = 0; q < HID / 4; q++) {
            ulonglong2 vA = hA[q], vB = hB[q];
            FMA2(p00, w[2 * q],     vA.x);
            FMA2(p01, w[2 * q + 1], vA.y);
            FMA2(p10, w[2 * q],     vB.x);
            FMA2(p11, w[2 * q + 1], vB.y);
        }
        uint64_t s0, s1;
        ADD2(s0, p00, p01);
        ADD2(s1, p10, p11);
        float lo0, hi0, lo1, hi1;
        UNPACK2(lo0, hi0, s0);
        UNPACK2(lo1, hi1, s1);
        const float z0 = lo0 + hi0;
        const float z1 = lo1 + hi1;

        // activations (gate_type warp-uniform)
        float a0, a1;
        if (gate_type == 2) { a0 = tanh_hw(z0);    a1 = tanh_hw(z1);    }
        else                { a0 = sigmoid_hw(z0); a1 = sigmoid_hw(z1); }
        sh_act[0][g] = a0;
        sh_act[1][g] = a1;
        __syncthreads();   // B1: acts visible; reads of sh_h/sh_x complete

        if (is_epi) {
            const float iv = sh_act[ech][ek];
            const float fv = sh_act[ech][HID + ek];
            const float gv = sh_act[ech][2 * HID + ek];
            const float ov = sh_act[ech][3 * HID + ek];
            c = fmaf(fv, c, iv * gv);
            const float hv = ov * tanh_hw(c);
            sh_h[ech][ek] = hv;
            atomicAdd(out_p,  hv * wl);   // RED.ADD.F32 (fire-and-forget)
            atomicAdd(lstm_p, hv);        // RED.ADD.F32
        }
        if (g < 32) sh_x[g >> 4][g & 15] = xreg;
        __syncthreads();   // B2: new sh_h/sh_x visible

        out_p  += BATCH * HEADS;
        lstm_p += BATCH * HID;
    }
}

extern "C" void kernel_launch(void* const* d_in, const int* in_sizes, int n_in,
                              void* d_out, int out_size) {
    const float* x     = (const float*)d_in[0];  // (T,B,I)
    const float* W_ih  = (const float*)d_in[1];  // (H,4h,I)
    const float* W_hh  = (const float*)d_in[2];  // (H,4h,h)
    const float* b_ih  = (const float*)d_in[3];  // (H,4h)
    const float* b_hh  = (const float*)d_in[4];  // (H,4h)
    const float* W_lin = (const float*)d_in[5];  // (H,h)
    const float* b_lin = (const float*)d_in[6];  // (H,)

    float* out      = (float*)d_out;                          // (T,B,H)
    float* lstm_out = out + (size_t)T_SEQ * BATCH * HEADS;    // (T,B,hid)

    const int n_tot = T_SEQ * BATCH * (HEADS + HID);
    init_out_kernel<<<(n_tot + 255) / 256, 256>>>(b_lin, (float*)d_out);
    lstm_chain2_kernel<<<BATCH * HEADS / 2, 256>>>(x, W_ih, W_hh, b_ih, b_hh,
                                                   W_lin, out, lstm_out);
}

// round 14
// speedup vs baseline: 1.9788x; 1.0343x over previous
#include <cuda_runtime.h>
#include <stdint.h>

#define T_SEQ 2048
#define BATCH 64
#define INPUT 16
#define HEADS 8
#define HID   64
#define GATES 256   // 4*HID

#define FMA2(acc, a, b) \
    asm("fma.rn.f32x2 %0, %1, %2, %0;" : "+l"(acc) : "l"(a), "l"(b))
#define ADD2(d, a, b) \
    asm("add.rn.f32x2 %0, %1, %2;" : "=l"(d) : "l"(a), "l"(b))
#define PACK2(d, lo, hi) \
    asm("mov.b64 %0, {%1, %2};" : "=l"(d) : "f"(lo), "f"(hi))
#define UNPACK2(lo, hi, s) \
    asm("mov.b64 {%0, %1}, %2;" : "=f"(lo), "=f"(hi) : "l"(s))

__device__ __forceinline__ float tanh_hw(float x) {
    float r;
    asm("tanh.approx.f32 %0, %1;" : "=f"(r) : "f"(x));
    return r;
}
// sigmoid(x) = 0.5*tanh(x/2) + 0.5
__device__ __forceinline__ float sigmoid_hw(float x) {
    return fmaf(0.5f, tanh_hw(0.5f * x), 0.5f);
}

// Pre-fill outputs: out[t,b,h] = b_lin[h]; lstm_out = 0. (d_out is poisoned.)
__global__ __launch_bounds__(256)
void init_out_kernel(const float* __restrict__ b_lin, float* __restrict__ o) {
    const int idx = blockIdx.x * 256 + threadIdx.x;
    const int n_out = T_SEQ * BATCH * HEADS;
    const int n_tot = n_out + T_SEQ * BATCH * HID;
    if (idx < n_out)      o[idx] = b_lin[idx & 7];
    else if (idx < n_tot) o[idx] = 0.0f;
}

// One CTA per (head, batch-pair): 2 chains sharing register weights.
// Phase-overlapped: main phase = h-dot only (acc init from xacc computed
// last step); post-B1 phase = epilogue (warps 0-3) + x-dot for t+1 (all
// warps, filling the previously idle epilogue shadow).
__global__ __launch_bounds__(256, 2)
void lstm_chain2_kernel(const float* __restrict__ x,
                        const float* __restrict__ W_ih,
                        const float* __restrict__ W_hh,
                        const float* __restrict__ b_ih,
                        const float* __restrict__ b_hh,
                        const float* __restrict__ W_lin,
                        float* __restrict__ out,       // (T,B,H)
                        float* __restrict__ lstm_out)  // (T,B,HID)
{
    const int h  = blockIdx.x & 7;
    const int b0 = (blockIdx.x >> 3) * 2;
    const int g  = threadIdx.x;

    __shared__ __align__(16) float sh_h[2][2][HID];   // [parity][chain][k]
    __shared__ __align__(16) float sh_x[2][2][INPUT]; // [buf][chain][i]
    __shared__ float sh_act[2][GATES];                // [chain][gate-row]

    // Pack this gate row's weights into f32x2 registers (once).
    uint64_t w[HID / 2];    // 32 u64
    uint64_t xw[INPUT / 2]; // 8 u64
    {
        const float* wr = W_hh + (h * GATES + g) * HID;
#pragma unroll
        for (int q = 0; q < HID / 2; q++) PACK2(w[q], wr[2 * q], wr[2 * q + 1]);
        const float* xr = W_ih + (h * GATES + g) * INPUT;
#pragma unroll
        for (int q = 0; q < INPUT / 2; q++) PACK2(xw[q], xr[2 * q], xr[2 * q + 1]);
    }
    const float bias = b_ih[h * GATES + g] + b_hh[h * GATES + g];
    uint64_t bias2; PACK2(bias2, bias, 0.0f);

    // Epilogue role: threads 0-127. ch = g>>6, unit k = g&63.
    const int  ek  = g & 63;
    const int  ech = (g >> 6) & 1;
    const bool is_epi = (g < 128);
    const float wl = is_epi ? W_lin[h * HID + ek] : 0.0f;

    float c = 0.0f;
    if (is_epi) sh_h[0][ech][ek] = 0.0f;
    if (g < 64) {
        const int buf = g >> 5;          // time 0 / 1
        const int ch  = (g >> 4) & 1;
        const int i   = g & 15;
        sh_x[buf][ch][i] = x[(buf * BATCH + b0 + ch) * INPUT + i];
    }
    __syncthreads();

    // xacc for t=0 (bias folded in)
    uint64_t xacc0, xacc1;
    {
        uint64_t q00 = bias2, q01 = 0ull, q10 = bias2, q11 = 0ull;
        const ulonglong2* xA = (const ulonglong2*)sh_x[0][0];
        const ulonglong2* xB = (const ulonglong2*)sh_x[0][1];
#pragma unroll
        for (int q = 0; q < INPUT / 4; q++) {
            ulonglong2 vA = xA[q], vB = xB[q];
            FMA2(q00, xw[2 * q],     vA.x);
            FMA2(q01, xw[2 * q + 1], vA.y);
            FMA2(q10, xw[2 * q],     vB.x);
            FMA2(q11, xw[2 * q + 1], vB.y);
        }
        ADD2(xacc0, q00, q01);
        ADD2(xacc1, q10, q11);
    }

    const int gate_type = g >> 6;  // warp-uniform: 0:i 1:f 2:g 3:o

    float* out_p  = out + (size_t)(b0 + ech) * HEADS + h;
    float* lstm_p = lstm_out + (size_t)(b0 + ech) * HID + ek;

#pragma unroll 1
    for (int t = 0; t < T_SEQ; t++) {
        const int hp = t & 1;

        // Prefetch x_{t+2} (threads 0-31), hidden under the h-dot.
        float xreg = 0.0f;
        if (g < 32 && t + 2 < T_SEQ)
            xreg = x[((t + 2) * BATCH + b0 + (g >> 4)) * INPUT + (g & 15)];

        // ---- main phase: h-dot only; accumulators seeded with xacc ----
        uint64_t p00 = xacc0, p01 = 0ull;
        uint64_t p10 = xacc1, p11 = 0ull;
        const ulonglong2* hA = (const ulonglong2*)sh_h[hp][0];
        const ulonglong2* hB = (const ulonglong2*)sh_h[hp][1];
#pragma unroll
        for (int q = 0; q < HID / 4; q++) {
            ulonglong2 vA = hA[q], vB = hB[q];
            FMA2(p00, w[2 * q],     vA.x);
            FMA2(p01, w[2 * q + 1], vA.y);
            FMA2(p10, w[2 * q],     vB.x);
            FMA2(p11, w[2 * q + 1], vB.y);
        }
        uint64_t s0, s1;
        ADD2(s0, p00, p01);
        ADD2(s1, p10, p11);
        float lo0, hi0, lo1, hi1;
        UNPACK2(lo0, hi0, s0);
        UNPACK2(lo1, hi1, s1);
        const float z0 = lo0 + hi0;
        const float z1 = lo1 + hi1;

        float a0, a1;
        if (gate_type == 2) { a0 = tanh_hw(z0);    a1 = tanh_hw(z1);    }
        else                { a0 = sigmoid_hw(z0); a1 = sigmoid_hw(z1); }
        sh_act[0][g] = a0;
        sh_act[1][g] = a1;
        __syncthreads();   // B1: all acts visible

        // ---- post phase: epilogue (warps 0-3) + x-dot t+1 (all warps) ----
        if (is_epi) {
            // thread k (ech=0) computed row k = i-gate -> a0 is i(chain0);
            // thread 64+k (ech=1) computed row 64+k = f-gate -> a1 is f(chain1)
            float iv, fv;
            if (ech == 0) { iv = a0; fv = sh_act[0][HID + ek]; }
            else          { fv = a1; iv = sh_act[1][ek]; }
            const float gv = sh_act[ech][2 * HID + ek];
            const float ov = sh_act[ech][3 * HID + ek];
            c = fmaf(fv, c, iv * gv);
            const float hv = ov * tanh_hw(c);
            sh_h[1 - hp][ech][ek] = hv;
            atomicAdd(out_p,  hv * wl);   // RED.ADD.F32 (fire-and-forget)
            atomicAdd(lstm_p, hv);        // RED.ADD.F32
        }
        {
            // xacc_{t+1} from sh_x[(t+1)&1] (holds x_{t+1})
            const int xb = (t + 1) & 1;
            uint64_t q00 = bias2, q01 = 0ull, q10 = bias2, q11 = 0ull;
            const ulonglong2* xA = (const ulonglong2*)sh_x[xb][0];
            const ulonglong2* xB = (const ulonglong2*)sh_x[xb][1];
#pragma unroll
            for (int q = 0; q < INPUT / 4; q++) {
                ulonglong2 vA = xA[q], vB = xB[q];
                FMA2(q00, xw[2 * q],     vA.x);
                FMA2(q01, xw[2 * q + 1], vA.y);
                FMA2(q10, xw[2 * q],     vB.x);
                FMA2(q11, xw[2 * q + 1], vB.y);
            }
            ADD2(xacc0, q00, q01);
            ADD2(xacc1, q10, q11);
        }
        if (g < 32) sh_x[t & 1][g >> 4][g & 15] = xreg;  // x_{t+2}
        __syncthreads();   // B2: sh_h[1-hp], xacc inputs settled

        out_p  += BATCH * HEADS;
        lstm_p += BATCH * HID;
    }
}

extern "C" void kernel_launch(void* const* d_in, const int* in_sizes, int n_in,
                              void* d_out, int out_size) {
    const float* x     = (const float*)d_in[0];  // (T,B,I)
    const float* W_ih  = (const float*)d_in[1];  // (H,4h,I)
    const float* W_hh  = (const float*)d_in[2];  // (H,4h,h)
    const float* b_ih  = (const float*)d_in[3];  // (H,4h)
    const float* b_hh  = (const float*)d_in[4];  // (H,4h)
    const float* W_lin = (const float*)d_in[5];  // (H,h)
    const float* b_lin = (const float*)d_in[6];  // (H,)

    float* out      = (float*)d_out;                          // (T,B,H)
    float* lstm_out = out + (size_t)T_SEQ * BATCH * HEADS;    // (T,B,hid)

    const int n_tot = T_SEQ * BATCH * (HEADS + HID);
    init_out_kernel<<<(n_tot + 255) / 256, 256>>>(b_lin, (float*)d_out);
    lstm_chain2_kernel<<<BATCH * HEADS / 2, 256>>>(x, W_ih, W_hh, b_ih, b_hh,
                                                   W_lin, out, lstm_out);
}